// round 4
// baseline (speedup 1.0000x reference)
#include <cuda_runtime.h>
#include <cuda_bf16.h>
#include <math.h>

#define S_TOK 8192
#define DM    1024
#define DFF   2048
#define NE    64
#define CAP   512

// ---------------- scratch (static device globals; no allocation) ----------------
__device__ float g_xn[(size_t)S_TOK * DM];            // 32 MB  normalized tokens
__device__ float g_h [(size_t)NE * CAP * DFF];        // 256 MB expert hidden
__device__ float g_od[(size_t)NE * CAP * DM];         // 128 MB expert output
__device__ int   g_cnt[NE];
__device__ int   g_tok[NE * CAP];                     // expert slot -> token
__device__ int   g_pairpos[S_TOK * 2];                // token pair -> e*CAP+pos (-1 dropped)
__device__ float g_pairw [S_TOK * 2];                 // router weights

// ---------------- helpers ----------------
__device__ __forceinline__ unsigned f2tf32(float x) {
    unsigned y;
    asm("cvt.rna.tf32.f32 %0, %1;" : "=r"(y) : "f"(x));
    return y;
}

__device__ __forceinline__ void mma_tf32(float d[4], const unsigned a[4], const unsigned b[2]) {
    asm volatile(
        "mma.sync.aligned.m16n8k8.row.col.f32.tf32.tf32.f32 "
        "{%0,%1,%2,%3}, {%4,%5,%6,%7}, {%8,%9}, {%0,%1,%2,%3};"
        : "+f"(d[0]), "+f"(d[1]), "+f"(d[2]), "+f"(d[3])
        : "r"(a[0]), "r"(a[1]), "r"(a[2]), "r"(a[3]), "r"(b[0]), "r"(b[1]));
}

// ---------------- K1: RMSNorm ----------------
__global__ __launch_bounds__(256) void rmsnorm_kernel(const float* __restrict__ x,
                                                      const float* __restrict__ w) {
    const int t = blockIdx.x;
    const int tid = threadIdx.x;
    float4 v = ((const float4*)(x + (size_t)t * DM))[tid];
    float ss = v.x * v.x + v.y * v.y + v.z * v.z + v.w * v.w;
#pragma unroll
    for (int o = 16; o; o >>= 1) ss += __shfl_xor_sync(0xffffffffu, ss, o);
    __shared__ float red[8];
    if ((tid & 31) == 0) red[tid >> 5] = ss;
    __syncthreads();
    float tot = 0.f;
#pragma unroll
    for (int i = 0; i < 8; i++) tot += red[i];
    const float scale = rsqrtf(tot * (1.0f / DM) + 1e-6f);
    float4 wv = ((const float4*)w)[tid];
    float4 o;
    o.x = v.x * scale * wv.x; o.y = v.y * scale * wv.y;
    o.z = v.z * scale * wv.z; o.w = v.w * scale * wv.w;
    ((float4*)(g_xn + (size_t)t * DM))[tid] = o;
}

// ---------------- K2: zero counters ----------------
__global__ void zero_cnt_kernel() {
    if (threadIdx.x < NE) g_cnt[threadIdx.x] = 0;
}

// ---------------- K3: router GEMM + top2 + softmax + dispatch-assign ----------------
// 64 tokens per block, 64 experts. scores = xn @ router_w^T
__global__ __launch_bounds__(256) void router_kernel(const float* __restrict__ rw) {
    __shared__ float As[64][20];
    __shared__ float Bs[64][20];
    __shared__ float Sc[64][65];

    const int tid = threadIdx.x;
    const int tBase = blockIdx.x * 64;
    const int r = tid >> 2, c4 = (tid & 3) * 4;
    const int tm = (tid >> 4) * 4, tn = (tid & 15) * 4;

    float acc[4][4];
#pragma unroll
    for (int i = 0; i < 4; i++)
#pragma unroll
        for (int j = 0; j < 4; j++) acc[i][j] = 0.f;

    for (int kt = 0; kt < DM; kt += 16) {
        *(float4*)&As[r][c4] = *(const float4*)(g_xn + (size_t)(tBase + r) * DM + kt + c4);
        *(float4*)&Bs[r][c4] = *(const float4*)(rw + (size_t)r * DM + kt + c4);
        __syncthreads();
#pragma unroll
        for (int k = 0; k < 16; k++) {
            float a[4], b[4];
#pragma unroll
            for (int i = 0; i < 4; i++) { a[i] = As[tm + i][k]; b[i] = Bs[tn + i][k]; }
#pragma unroll
            for (int i = 0; i < 4; i++)
#pragma unroll
                for (int j = 0; j < 4; j++) acc[i][j] += a[i] * b[j];
        }
        __syncthreads();
    }
#pragma unroll
    for (int i = 0; i < 4; i++)
#pragma unroll
        for (int j = 0; j < 4; j++) Sc[tm + i][tn + j] = acc[i][j];
    __syncthreads();

    const int warp = tid >> 5, lane = tid & 31;
    for (int tt = 0; tt < 8; ++tt) {
        const int trow = warp * 8 + tt;
        float v1 = Sc[trow][lane];      int i1 = lane;
        float v2 = Sc[trow][lane + 32]; int i2 = lane + 32;
        if (v2 > v1) { float tv = v1; v1 = v2; v2 = tv; int ti = i1; i1 = i2; i2 = ti; }
#pragma unroll
        for (int off = 16; off; off >>= 1) {
            float o1 = __shfl_down_sync(0xffffffffu, v1, off);
            int  oi1 = __shfl_down_sync(0xffffffffu, i1, off);
            float o2 = __shfl_down_sync(0xffffffffu, v2, off);
            int  oi2 = __shfl_down_sync(0xffffffffu, i2, off);
            if (o1 > v1) {
                if (v1 >= o2) { v2 = v1; i2 = i1; } else { v2 = o2; i2 = oi2; }
                v1 = o1; i1 = oi1;
            } else if (o1 > v2) { v2 = o1; i2 = oi1; }
        }
        if (lane == 0) {
            const int token = tBase + trow;
            const float p1 = 1.0f / (1.0f + expf(v2 - v1));
            const float p2 = 1.0f - p1;
            int pos = atomicAdd(&g_cnt[i1], 1);
            int pp = -1;
            if (pos < CAP) { g_tok[i1 * CAP + pos] = token; pp = i1 * CAP + pos; }
            g_pairpos[token * 2] = pp; g_pairw[token * 2] = p1;
            pos = atomicAdd(&g_cnt[i2], 1);
            pp = -1;
            if (pos < CAP) { g_tok[i2 * CAP + pos] = token; pp = i2 * CAP + pos; }
            g_pairpos[token * 2 + 1] = pp; g_pairw[token * 2 + 1] = p2;
        }
    }
}

// ---------------- K4/K5: grouped expert GEMM (tf32 mma), 128x128x16 tiles ----------------
// PHASE1: h[e,r,:] = silu(xn[tok[e,r],:] @ w1[e]^T)   (M<=cnt, N=DFF, K=DM)
// PHASE2: od[e,r,:] = h[e,r,:] @ w2[e]^T              (M<=cnt, N=DM,  K=DFF)
template <bool PHASE1>
__global__ __launch_bounds__(256) void gemm_expert(const float* __restrict__ Bbase) {
    constexpr int Kdim = PHASE1 ? DM : DFF;
    constexpr int N    = PHASE1 ? DFF : DM;

    const int e = blockIdx.z;
    const int cnt = min(g_cnt[e], CAP);
    const int rowBase = blockIdx.y * 128;
    if (rowBase >= cnt) return;
    const int colBase = blockIdx.x * 128;

    const float* B = Bbase + (size_t)e * N * Kdim + (size_t)colBase * Kdim;
    float* C = (PHASE1 ? g_h : g_od) + (size_t)e * CAP * N;

    __shared__ unsigned As[2][128][20];
    __shared__ unsigned Bs[2][128][20];

    const int tid = threadIdx.x;
    const int c4 = (tid & 3) * 4;

    const float* aPtr[2];
    const float* bPtr[2];
#pragma unroll
    for (int it = 0; it < 2; ++it) {
        const int r = (tid + it * 256) >> 2;
        const int grow = rowBase + r;
        if (grow < cnt) {
            if (PHASE1) aPtr[it] = g_xn + (size_t)g_tok[e * CAP + grow] * Kdim;
            else        aPtr[it] = g_h + ((size_t)e * CAP + grow) * Kdim;
        } else {
            aPtr[it] = nullptr;
        }
        bPtr[it] = B + (size_t)r * Kdim;
    }

    float4 aReg[2], bReg[2];

    auto ldTile = [&](int kt) {
        const int off = kt * 16 + c4;
#pragma unroll
        for (int it = 0; it < 2; ++it) {
            aReg[it] = aPtr[it] ? *(const float4*)(aPtr[it] + off)
                                : make_float4(0.f, 0.f, 0.f, 0.f);
            bReg[it] = *(const float4*)(bPtr[it] + off);
        }
    };
    auto stTile = [&](int buf) {
#pragma unroll
        for (int it = 0; it < 2; ++it) {
            const int r = (tid + it * 256) >> 2;
            uint4 av, bv;
            av.x = f2tf32(aReg[it].x); av.y = f2tf32(aReg[it].y);
            av.z = f2tf32(aReg[it].z); av.w = f2tf32(aReg[it].w);
            bv.x = f2tf32(bReg[it].x); bv.y = f2tf32(bReg[it].y);
            bv.z = f2tf32(bReg[it].z); bv.w = f2tf32(bReg[it].w);
            *(uint4*)&As[buf][r][c4] = av;
            *(uint4*)&Bs[buf][r][c4] = bv;
        }
    };

    const int warp = tid >> 5, lane = tid & 31;
    const int wm = warp & 3, wn = warp >> 2;   // 4 (m) x 2 (n) warp grid
    const int mW = wm * 32, nW = wn * 64;
    const int g = lane >> 2, t = lane & 3;

    float acc[2][8][4];
#pragma unroll
    for (int im = 0; im < 2; ++im)
#pragma unroll
        for (int in_ = 0; in_ < 8; ++in_)
#pragma unroll
            for (int q = 0; q < 4; ++q) acc[im][in_][q] = 0.f;

    auto compute = [&](int buf) {
#pragma unroll
        for (int ks = 0; ks < 16; ks += 8) {
            unsigned a[2][4], b[8][2];
#pragma unroll
            for (int im = 0; im < 2; ++im) {
                const int r0 = mW + im * 16 + g;
                a[im][0] = As[buf][r0    ][ks + t];
                a[im][1] = As[buf][r0 + 8][ks + t];
                a[im][2] = As[buf][r0    ][ks + t + 4];
                a[im][3] = As[buf][r0 + 8][ks + t + 4];
            }
#pragma unroll
            for (int in_ = 0; in_ < 8; ++in_) {
                const int n0 = nW + in_ * 8 + g;
                b[in_][0] = Bs[buf][n0][ks + t];
                b[in_][1] = Bs[buf][n0][ks + t + 4];
            }
#pragma unroll
            for (int im = 0; im < 2; ++im)
#pragma unroll
                for (int in_ = 0; in_ < 8; ++in_)
                    mma_tf32(acc[im][in_], a[im], b[in_]);
        }
    };

    const int KT = Kdim >> 4;
    ldTile(0);
    stTile(0);
    __syncthreads();
    int buf = 0;
    for (int kt = 0; kt < KT; ++kt) {
        const bool more = (kt + 1 < KT);
        if (more) ldTile(kt + 1);
        compute(buf);
        if (more) stTile(buf ^ 1);
        __syncthreads();
        buf ^= 1;
    }

    // epilogue (+ silu for phase 1)
#pragma unroll
    for (int im = 0; im < 2; ++im) {
        const int r0 = rowBase + mW + im * 16 + g;
#pragma unroll
        for (int in_ = 0; in_ < 8; ++in_) {
            const int col = colBase + nW + in_ * 8 + t * 2;
            const float* d = acc[im][in_];
            if (r0 < cnt) {
                float v0 = d[0], v1 = d[1];
                if (PHASE1) {
                    v0 = v0 / (1.f + expf(-v0));
                    v1 = v1 / (1.f + expf(-v1));
                }
                *(float2*)&C[(size_t)r0 * N + col] = make_float2(v0, v1);
            }
            const int r1 = r0 + 8;
            if (r1 < cnt) {
                float v0 = d[2], v1 = d[3];
                if (PHASE1) {
                    v0 = v0 / (1.f + expf(-v0));
                    v1 = v1 / (1.f + expf(-v1));
                }
                *(float2*)&C[(size_t)r1 * N + col] = make_float2(v0, v1);
            }
        }
    }
}

// ---------------- K6: combine (residual + weighted gather, no atomics) ----------------
__global__ __launch_bounds__(256) void combine_kernel(const float* __restrict__ x,
                                                      float* __restrict__ out) {
    const int t = blockIdx.x;
    const int tid = threadIdx.x;
    float4 v = ((const float4*)(x + (size_t)t * DM))[tid];
    const int p0 = g_pairpos[t * 2];
    const int p1 = g_pairpos[t * 2 + 1];
    const float w0 = g_pairw[t * 2];
    const float w1 = g_pairw[t * 2 + 1];
    if (p0 >= 0) {
        float4 o = ((const float4*)(g_od + (size_t)p0 * DM))[tid];
        v.x += w0 * o.x; v.y += w0 * o.y; v.z += w0 * o.z; v.w += w0 * o.w;
    }
    if (p1 >= 0) {
        float4 o = ((const float4*)(g_od + (size_t)p1 * DM))[tid];
        v.x += w1 * o.x; v.y += w1 * o.y; v.z += w1 * o.z; v.w += w1 * o.w;
    }
    ((float4*)(out + (size_t)t * DM))[tid] = v;
}

// ---------------- launch ----------------
extern "C" void kernel_launch(void* const* d_in, const int* in_sizes, int n_in,
                              void* d_out, int out_size) {
    const float* x    = (const float*)d_in[0];
    const float* rmsw = (const float*)d_in[1];
    const float* rw   = (const float*)d_in[2];
    const float* w1   = (const float*)d_in[3];
    const float* w2   = (const float*)d_in[4];
    float* out = (float*)d_out;

    rmsnorm_kernel<<<S_TOK, 256>>>(x, rmsw);
    zero_cnt_kernel<<<1, 64>>>();
    router_kernel<<<S_TOK / 64, 256>>>(rw);

    dim3 g1(DFF / 128, CAP / 128, NE);
    gemm_expert<true><<<g1, 256>>>(w1);

    dim3 g2(DM / 128, CAP / 128, NE);
    gemm_expert<false><<<g2, 256>>>(w2);

    combine_kernel<<<S_TOK, 256>>>(x, out);
}